// round 4
// baseline (speedup 1.0000x reference)
#include <cuda_runtime.h>

#define BATCH  32
#define IMG_H  512
#define IMG_W  512
#define TILES  8
#define TSZ    64          // 512 / 8
#define NBINS  256
#define NT     (BATCH * TILES * TILES)   // 2048 tiles
#define PLANE  (IMG_H * IMG_W)           // 262144
#define CLIPV  640                        // floor(40.0 * 4096 / 256)

// XLA rewrites x/const -> x * (1/const). Replicate with the same f32 constants.
#define INV255 (1.0f / 255.0f)
#define INV60  (1.0f / 60.0f)

// Scratch (static device globals — no allocation in kernel_launch)
__device__ unsigned int  g_hls [BATCH * PLANE];   // packed H | L<<8 | S<<16   (33.5 MB)
__device__ int           g_hist[NT * NBINS];      // per-tile histograms       (2 MB)
__device__ unsigned char g_lut [NT * NBINS];      // per-tile LUTs             (512 KB)

// IEEE ops, no FMA contraction (XLA emits uncontracted mul/add and IEEE div
// for non-constant divisors)
__device__ __forceinline__ float fdiv(float a, float b) { return __fdiv_rn(a, b); }
__device__ __forceinline__ float fmul(float a, float b) { return __fmul_rn(a, b); }
__device__ __forceinline__ float fadd(float a, float b) { return __fadd_rn(a, b); }
__device__ __forceinline__ float fsub(float a, float b) { return __fsub_rn(a, b); }

// ---------------------------------------------------------------------------
// Kernel 1: quantize + RGB->HLS (u8) + per-tile histogram.
// One block per tile (exclusive histogram ownership -> shared mem only).
// ---------------------------------------------------------------------------
__global__ __launch_bounds__(256) void k1_hls_hist(const float* __restrict__ img)
{
    __shared__ int hist[NBINS];
    const int tid = threadIdx.x;
    hist[tid] = 0;
    __syncthreads();

    const int gb = blockIdx.x;            // global tile id: b*64 + ty*8 + tx
    const int b  = gb >> 6;
    const int t  = gb & 63;
    const int ty = t >> 3, tx = t & 7;

    const float* rp = img + (size_t)b * 3 * PLANE;
    const float* gp = rp + PLANE;
    const float* bp = gp + PLANE;

    const int lx  = tid & 63;
    const int ly0 = tid >> 6;              // 0..3

    #pragma unroll 4
    for (int i = 0; i < 16; i++) {
        const int ly  = ly0 + i * 4;
        const int y   = ty * TSZ + ly;
        const int x   = tx * TSZ + lx;
        const int off = y * IMG_W + x;

        // q = clip(floor(img), 0, 255); x = q * (1/255)   (XLA reciprocal-mul)
        float r  = fmul(fminf(fmaxf(floorf(rp[off]), 0.f), 255.f), INV255);
        float g  = fmul(fminf(fmaxf(floorf(gp[off]), 0.f), 255.f), INV255);
        float bl = fmul(fminf(fmaxf(floorf(bp[off]), 0.f), 255.f), INV255);

        float vmax = fmaxf(fmaxf(r, g), bl);
        float vmin = fminf(fminf(r, g), bl);
        float l    = fmul(fadd(vmax, vmin), 0.5f);
        float diff = fsub(vmax, vmin);
        float denom = (l < 0.5f) ? fadd(vmax, vmin) : fsub(fsub(2.0f, vmax), vmin);
        float s    = (diff > 0.f) ? fdiv(diff, fmaxf(denom, 1e-12f)) : 0.f;  // non-const div
        float safe = fmaxf(diff, 1e-12f);

        float h;
        if (vmax == r)      h = fdiv(fmul(60.f, fsub(g, bl)), safe);
        else if (vmax == g) h = fadd(120.f, fdiv(fmul(60.f, fsub(bl, r)), safe));
        else                h = fadd(240.f, fdiv(fmul(60.f, fsub(r, g)), safe));
        if (!(diff > 0.f))  h = 0.f;
        if (h < 0.f)        h = fadd(h, 360.f);

        int H8 = (int)fminf(fmaxf(rintf(fmul(h, 0.5f)),  0.f), 255.f);
        int L8 = (int)fminf(fmaxf(rintf(fmul(l, 255.f)), 0.f), 255.f);
        int S8 = (int)fminf(fmaxf(rintf(fmul(s, 255.f)), 0.f), 255.f);

        atomicAdd(&hist[L8], 1);
        g_hls[(size_t)b * PLANE + off] =
            (unsigned)H8 | ((unsigned)L8 << 8) | ((unsigned)S8 << 16);
    }
    __syncthreads();
    g_hist[gb * NBINS + tid] = hist[tid];
}

// ---------------------------------------------------------------------------
// Kernel 2: clip + excess redistribution + inclusive scan -> LUT (u8)
// ---------------------------------------------------------------------------
__global__ __launch_bounds__(256) void k2_lut()
{
    __shared__ int sh[NBINS];
    const int tid  = threadIdx.x;
    const int tgid = blockIdx.x;

    int h = g_hist[tgid * NBINS + tid];

    // total excess (reduction)
    sh[tid] = max(h - CLIPV, 0);
    __syncthreads();
    for (int off = 128; off > 0; off >>= 1) {
        if (tid < off) sh[tid] += sh[tid + off];
        __syncthreads();
    }
    const int excess = sh[0];
    __syncthreads();

    h = min(h, CLIPV) + excess / NBINS;
    const int residual = excess % NBINS;
    const int step = max(NBINS / max(residual, 1), 1);
    if (residual > 0 && (tid % step) == 0 && (tid / step) < residual) h += 1;

    // inclusive scan (Hillis–Steele)
    sh[tid] = h;
    __syncthreads();
    for (int off = 1; off < NBINS; off <<= 1) {
        int v = (tid >= off) ? sh[tid - off] : 0;
        __syncthreads();
        sh[tid] += v;
        __syncthreads();
    }

    // scale = 255/4096 exactly representable; cdf*scale < 2^24 -> exact mul
    float lv = rintf(fmul((float)sh[tid], 255.0f / 4096.0f));
    g_lut[tgid * NBINS + tid] = (unsigned char)fminf(fmaxf(lv, 0.f), 255.f);
}

// ---------------------------------------------------------------------------
// Kernel 3: bilinear LUT interpolation + HLS->RGB, 4 px / thread
// ---------------------------------------------------------------------------
__device__ __forceinline__ float hue_fn(float p1, float p2, float h)
{
    float m = fmodf(h, 360.f);
    if (m < 0.f) m = fadd(m, 360.f);       // jnp.mod semantics (exact here)
    float hh = fmul(m, INV60);             // XLA: mod(...)/60 -> mul by 1/60
    float d  = fsub(p2, p1);
    if (hh < 1.f) return fadd(p1, fmul(d, hh));
    if (hh < 3.f) return p2;
    if (hh < 4.f) return fadd(p1, fmul(d, fsub(4.f, hh)));
    return p1;
}

__global__ __launch_bounds__(256) void k3_apply(float* __restrict__ out)
{
    const int gid = blockIdx.x * blockDim.x + threadIdx.x;
    const int p   = gid * 4;
    const int b   = p / PLANE;
    const int rem = p % PLANE;
    const int y   = rem >> 9;
    const int x0  = rem & 511;

    // vertical interp coords (shared by the 4 pixels); /64 exact
    float tyf  = (float)y * (1.0f / TSZ) - 0.5f;
    float ty1f = floorf(tyf);
    float ya   = tyf - ty1f;
    int ty1 = (int)ty1f;
    int ty2 = min(ty1 + 1, TILES - 1);
    ty1 = max(ty1, 0);

    const unsigned char* lutb = g_lut + (size_t)b * TILES * TILES * NBINS;

    const uint4 hls4 = *reinterpret_cast<const uint4*>(&g_hls[(size_t)b * PLANE + rem]);
    const unsigned vals[4] = { hls4.x, hls4.y, hls4.z, hls4.w };

    float ro[4], go[4], bo[4];
    #pragma unroll
    for (int j = 0; j < 4; j++) {
        const int x = x0 + j;
        const unsigned pk = vals[j];
        const int H8 = pk & 255, L8 = (pk >> 8) & 255, S8 = (pk >> 16) & 255;

        float txf  = (float)x * (1.0f / TSZ) - 0.5f;
        float tx1f = floorf(txf);
        float xa   = txf - tx1f;
        int tx1 = (int)tx1f;
        int tx2 = min(tx1 + 1, TILES - 1);
        tx1 = max(tx1, 0);

        float g00 = lutb[(ty1 * TILES + tx1) * NBINS + L8];
        float g01 = lutb[(ty1 * TILES + tx2) * NBINS + L8];
        float g10 = lutb[(ty2 * TILES + tx1) * NBINS + L8];
        float g11 = lutb[(ty2 * TILES + tx2) * NBINS + L8];

        // All terms exactly representable (u8 * dyadic/64 * dyadic/64);
        // sum exact under any op order -> matches reference bit-exactly.
        float res = g00 * (1.f - xa) * (1.f - ya) + g01 * xa * (1.f - ya)
                  + g10 * (1.f - xa) * ya         + g11 * xa * ya;
        float Lnew = fminf(fmaxf(rintf(res), 0.f), 255.f);

        // HLS -> RGB (reciprocal-mul for /255, no FMA contraction)
        float hd = (float)H8 * 2.0f;
        float l  = fmul(Lnew, INV255);
        float s  = fmul((float)S8, INV255);
        float p2 = (l <= 0.5f) ? fmul(l, fadd(1.f, s))
                               : fsub(fadd(l, s), fmul(l, s));
        float p1 = fsub(fmul(2.f, l), p2);

        float r  = hue_fn(p1, p2, hd + 120.f);
        float g  = hue_fn(p1, p2, hd);
        float bb = hue_fn(p1, p2, hd - 120.f);
        if (!(s > 0.f)) { r = l; g = l; bb = l; }

        ro[j] = fminf(fmaxf(rintf(fmul(r,  255.f)), 0.f), 255.f);
        go[j] = fminf(fmaxf(rintf(fmul(g,  255.f)), 0.f), 255.f);
        bo[j] = fminf(fmaxf(rintf(fmul(bb, 255.f)), 0.f), 255.f);
    }

    float* op = out + (size_t)b * 3 * PLANE + rem;
    *reinterpret_cast<float4*>(op)             = make_float4(ro[0], ro[1], ro[2], ro[3]);
    *reinterpret_cast<float4*>(op + PLANE)     = make_float4(go[0], go[1], go[2], go[3]);
    *reinterpret_cast<float4*>(op + 2 * PLANE) = make_float4(bo[0], bo[1], bo[2], bo[3]);
}

// ---------------------------------------------------------------------------
extern "C" void kernel_launch(void* const* d_in, const int* in_sizes, int n_in,
                              void* d_out, int out_size)
{
    (void)in_sizes; (void)n_in; (void)out_size;
    const float* img = (const float*)d_in[0];
    float* out = (float*)d_out;

    k1_hls_hist<<<NT, 256>>>(img);
    k2_lut<<<NT, 256>>>();
    k3_apply<<<(BATCH * PLANE / 4) / 256, 256>>>(out);
}

// round 5
// speedup vs baseline: 1.1579x; 1.1579x over previous
#include <cuda_runtime.h>

#define BATCH  32
#define IMG_H  512
#define IMG_W  512
#define TILES  8
#define TSZ    64          // 512 / 8
#define NBINS  256
#define NT     (BATCH * TILES * TILES)   // 2048 tiles
#define PLANE  (IMG_H * IMG_W)           // 262144
#define CLIPV  640                        // floor(40.0 * 4096 / 256)

// XLA rewrites x/const -> x * (1/const). Replicate with the same f32 constants.
#define INV255 (1.0f / 255.0f)
#define INV60  (1.0f / 60.0f)

// Scratch (static device globals — no allocation in kernel_launch)
__device__ unsigned int  g_hls[BATCH * PLANE];    // packed H | L<<8 | S<<16   (33.5 MB)
__device__ unsigned char g_lut[NT * NBINS];       // per-tile LUTs             (512 KB)

// IEEE ops, no FMA contraction (match XLA elementwise emission)
__device__ __forceinline__ float fdiv(float a, float b) { return __fdiv_rn(a, b); }
__device__ __forceinline__ float fmul(float a, float b) { return __fmul_rn(a, b); }
__device__ __forceinline__ float fadd(float a, float b) { return __fadd_rn(a, b); }
__device__ __forceinline__ float fsub(float a, float b) { return __fsub_rn(a, b); }

__device__ __forceinline__ unsigned hls_pixel(float rq, float gq, float bq, int* L8out)
{
    // inputs already clip(floor(v),0,255); x = q * (1/255)
    float r  = fmul(rq, INV255);
    float g  = fmul(gq, INV255);
    float bl = fmul(bq, INV255);

    float vmax = fmaxf(fmaxf(r, g), bl);
    float vmin = fminf(fminf(r, g), bl);
    float l    = fmul(fadd(vmax, vmin), 0.5f);
    float diff = fsub(vmax, vmin);
    float denom = (l < 0.5f) ? fadd(vmax, vmin) : fsub(fsub(2.0f, vmax), vmin);
    float s    = (diff > 0.f) ? fdiv(diff, fmaxf(denom, 1e-12f)) : 0.f;
    float safe = fmaxf(diff, 1e-12f);

    float h;
    if (vmax == r)      h = fdiv(fmul(60.f, fsub(g, bl)), safe);
    else if (vmax == g) h = fadd(120.f, fdiv(fmul(60.f, fsub(bl, r)), safe));
    else                h = fadd(240.f, fdiv(fmul(60.f, fsub(r, g)), safe));
    if (!(diff > 0.f))  h = 0.f;
    if (h < 0.f)        h = fadd(h, 360.f);

    int H8 = (int)fminf(fmaxf(rintf(fmul(h, 0.5f)),  0.f), 255.f);
    int L8 = (int)fminf(fmaxf(rintf(fmul(l, 255.f)), 0.f), 255.f);
    int S8 = (int)fminf(fmaxf(rintf(fmul(s, 255.f)), 0.f), 255.f);

    *L8out = L8;
    return (unsigned)H8 | ((unsigned)L8 << 8) | ((unsigned)S8 << 16);
}

// ---------------------------------------------------------------------------
// Kernel 1: quantize + RGB->HLS (u8) + per-tile histogram + clip/scan -> LUT.
// One block per tile. float4 loads, uint4 packed HLS stores, fused LUT build.
// ---------------------------------------------------------------------------
__global__ __launch_bounds__(256) void k1_hls_hist_lut(const float* __restrict__ img)
{
    __shared__ int hist[NBINS];
    const int tid = threadIdx.x;
    hist[tid] = 0;
    __syncthreads();

    const int gb = blockIdx.x;            // global tile id: b*64 + ty*8 + tx
    const int b  = gb >> 6;
    const int t  = gb & 63;
    const int ty = t >> 3, tx = t & 7;

    const float4* rp = reinterpret_cast<const float4*>(img + (size_t)b * 3 * PLANE);
    const float4* gp = rp + PLANE / 4;
    const float4* bp = gp + PLANE / 4;
    uint4* hlsp = reinterpret_cast<uint4*>(g_hls) + (size_t)b * (PLANE / 4);

    const int fv   = tid & 15;             // float4 index within tile row (16 per row)
    const int row0 = tid >> 4;             // 0..15

    #pragma unroll
    for (int pass = 0; pass < 4; pass++) {
        const int row  = row0 + pass * 16;
        const int y    = ty * TSZ + row;
        const int idx4 = y * (IMG_W / 4) + tx * (TSZ / 4) + fv;

        float4 r4 = rp[idx4];
        float4 g4 = gp[idx4];
        float4 b4 = bp[idx4];

        // quantize: clip(floor(v), 0, 255)
        r4.x = fminf(fmaxf(floorf(r4.x), 0.f), 255.f);
        r4.y = fminf(fmaxf(floorf(r4.y), 0.f), 255.f);
        r4.z = fminf(fmaxf(floorf(r4.z), 0.f), 255.f);
        r4.w = fminf(fmaxf(floorf(r4.w), 0.f), 255.f);
        g4.x = fminf(fmaxf(floorf(g4.x), 0.f), 255.f);
        g4.y = fminf(fmaxf(floorf(g4.y), 0.f), 255.f);
        g4.z = fminf(fmaxf(floorf(g4.z), 0.f), 255.f);
        g4.w = fminf(fmaxf(floorf(g4.w), 0.f), 255.f);
        b4.x = fminf(fmaxf(floorf(b4.x), 0.f), 255.f);
        b4.y = fminf(fmaxf(floorf(b4.y), 0.f), 255.f);
        b4.z = fminf(fmaxf(floorf(b4.z), 0.f), 255.f);
        b4.w = fminf(fmaxf(floorf(b4.w), 0.f), 255.f);

        int L0, L1, L2, L3;
        uint4 o;
        o.x = hls_pixel(r4.x, g4.x, b4.x, &L0);
        o.y = hls_pixel(r4.y, g4.y, b4.y, &L1);
        o.z = hls_pixel(r4.z, g4.z, b4.z, &L2);
        o.w = hls_pixel(r4.w, g4.w, b4.w, &L3);

        atomicAdd(&hist[L0], 1);
        atomicAdd(&hist[L1], 1);
        atomicAdd(&hist[L2], 1);
        atomicAdd(&hist[L3], 1);

        hlsp[idx4] = o;
    }
    __syncthreads();

    // ---- fused former k2: clip + excess redistribution + scan -> LUT ----
    int h = hist[tid];
    __syncthreads();

    hist[tid] = max(h - CLIPV, 0);
    __syncthreads();
    for (int off = 128; off > 0; off >>= 1) {
        if (tid < off) hist[tid] += hist[tid + off];
        __syncthreads();
    }
    const int excess = hist[0];
    __syncthreads();

    h = min(h, CLIPV) + excess / NBINS;
    const int residual = excess % NBINS;
    const int step = max(NBINS / max(residual, 1), 1);
    if (residual > 0 && (tid % step) == 0 && (tid / step) < residual) h += 1;

    // inclusive scan (Hillis–Steele)
    hist[tid] = h;
    __syncthreads();
    for (int off = 1; off < NBINS; off <<= 1) {
        int v = (tid >= off) ? hist[tid - off] : 0;
        __syncthreads();
        hist[tid] += v;
        __syncthreads();
    }

    // scale = 255/4096 exactly representable; cdf*scale < 2^24 -> exact mul
    float lv = rintf(fmul((float)hist[tid], 255.0f / 4096.0f));
    g_lut[gb * NBINS + tid] = (unsigned char)fminf(fmaxf(lv, 0.f), 255.f);
}

// ---------------------------------------------------------------------------
// Kernel 3: bilinear LUT interpolation + HLS->RGB, 4 px / thread
// ---------------------------------------------------------------------------
__device__ __forceinline__ float hue_fn(float p1, float p2, float h)
{
    // h integer-valued in [-120, 630]; conditional +-360 is bit-exact mod 360
    float m = h;
    if (m < 0.f)      m = fadd(m, 360.f);
    else if (m >= 360.f) m = fsub(m, 360.f);
    float hh = fmul(m, INV60);             // XLA: mod(...)/60 -> mul by 1/60
    float d  = fsub(p2, p1);
    if (hh < 1.f) return fadd(p1, fmul(d, hh));
    if (hh < 3.f) return p2;
    if (hh < 4.f) return fadd(p1, fmul(d, fsub(4.f, hh)));
    return p1;
}

__global__ __launch_bounds__(256) void k3_apply(float* __restrict__ out)
{
    const int gid = blockIdx.x * blockDim.x + threadIdx.x;
    const int p   = gid * 4;
    const int b   = p / PLANE;
    const int rem = p % PLANE;
    const int y   = rem >> 9;
    const int x0  = rem & 511;

    // vertical interp coords (shared by the 4 pixels); /64 exact
    float tyf  = (float)y * (1.0f / TSZ) - 0.5f;
    float ty1f = floorf(tyf);
    float ya   = tyf - ty1f;
    int ty1 = (int)ty1f;
    int ty2 = min(ty1 + 1, TILES - 1);
    ty1 = max(ty1, 0);

    const unsigned char* __restrict__ lutb = g_lut + (size_t)b * TILES * TILES * NBINS;

    const uint4 hls4 = *reinterpret_cast<const uint4*>(&g_hls[(size_t)b * PLANE + rem]);
    const unsigned vals[4] = { hls4.x, hls4.y, hls4.z, hls4.w };

    float ro[4], go[4], bo[4];
    #pragma unroll
    for (int j = 0; j < 4; j++) {
        const int x = x0 + j;
        const unsigned pk = vals[j];
        const int H8 = pk & 255, L8 = (pk >> 8) & 255, S8 = (pk >> 16) & 255;

        float txf  = (float)x * (1.0f / TSZ) - 0.5f;
        float tx1f = floorf(txf);
        float xa   = txf - tx1f;
        int tx1 = (int)tx1f;
        int tx2 = min(tx1 + 1, TILES - 1);
        tx1 = max(tx1, 0);

        float g00 = lutb[(ty1 * TILES + tx1) * NBINS + L8];
        float g01 = lutb[(ty1 * TILES + tx2) * NBINS + L8];
        float g10 = lutb[(ty2 * TILES + tx1) * NBINS + L8];
        float g11 = lutb[(ty2 * TILES + tx2) * NBINS + L8];

        // All terms exactly representable -> exact under any op order.
        float res = g00 * (1.f - xa) * (1.f - ya) + g01 * xa * (1.f - ya)
                  + g10 * (1.f - xa) * ya         + g11 * xa * ya;
        float Lnew = fminf(fmaxf(rintf(res), 0.f), 255.f);

        // HLS -> RGB (reciprocal-mul for /255, no FMA contraction)
        float hd = (float)H8 * 2.0f;
        float l  = fmul(Lnew, INV255);
        float s  = fmul((float)S8, INV255);
        float p2 = (l <= 0.5f) ? fmul(l, fadd(1.f, s))
                               : fsub(fadd(l, s), fmul(l, s));
        float p1 = fsub(fmul(2.f, l), p2);

        float r  = hue_fn(p1, p2, hd + 120.f);
        float g  = hue_fn(p1, p2, hd);
        float bb = hue_fn(p1, p2, hd - 120.f);
        if (!(s > 0.f)) { r = l; g = l; bb = l; }

        ro[j] = fminf(fmaxf(rintf(fmul(r,  255.f)), 0.f), 255.f);
        go[j] = fminf(fmaxf(rintf(fmul(g,  255.f)), 0.f), 255.f);
        bo[j] = fminf(fmaxf(rintf(fmul(bb, 255.f)), 0.f), 255.f);
    }

    float* op = out + (size_t)b * 3 * PLANE + rem;
    *reinterpret_cast<float4*>(op)             = make_float4(ro[0], ro[1], ro[2], ro[3]);
    *reinterpret_cast<float4*>(op + PLANE)     = make_float4(go[0], go[1], go[2], go[3]);
    *reinterpret_cast<float4*>(op + 2 * PLANE) = make_float4(bo[0], bo[1], bo[2], bo[3]);
}

// ---------------------------------------------------------------------------
extern "C" void kernel_launch(void* const* d_in, const int* in_sizes, int n_in,
                              void* d_out, int out_size)
{
    (void)in_sizes; (void)n_in; (void)out_size;
    const float* img = (const float*)d_in[0];
    float* out = (float*)d_out;

    k1_hls_hist_lut<<<NT, 256>>>(img);
    k3_apply<<<(BATCH * PLANE / 4) / 256, 256>>>(out);
}